// round 2
// baseline (speedup 1.0000x reference)
#include <cuda_runtime.h>

#define BATCH 2
#define NBOX  20000
#define CH    256
#define KTOP  5000
#define NPAD  32768
#define KP    5120
#define NLAYERS 6

// ---------------- scratch (no allocations allowed) ----------------
__device__ unsigned long long g_sort[BATCH * NPAD];
__device__ float        g_topS[BATCH * KTOP];
__device__ int          g_keep[BATCH * KTOP];
__device__ float4       g_boxk[BATCH * KTOP];
__device__ float        g_areak[BATCH * KTOP];
__device__ unsigned int g_flags[BATCH * KTOP];
__device__ float        g_x0[BATCH * CH * KP];
__device__ float        g_x1[BATCH * CH * KP];

// ---------------- 1) build sort keys ----------------
// key = score_bits << 32 | (0xFFFFFFFF - idx): descending sort gives
// descending score with ascending-index tie-break (== jax.lax.top_k).
__global__ void k_init(const float* __restrict__ score) {
    int i = blockIdx.x * blockDim.x + threadIdx.x;
    if (i >= BATCH * NPAD) return;
    int b = i >> 15, n = i & (NPAD - 1);
    unsigned long long key = 0ull;
    if (n < NBOX) {
        unsigned int bits = __float_as_uint(score[b * NBOX + n]); // scores in [0,1): positive
        key = ((unsigned long long)bits << 32) | (0xFFFFFFFFu - (unsigned)n);
    }
    g_sort[i] = key;
}

// Bitonic network, global descending. Direction of a compare in stage k is
// ((i & k) == 0) -> descending (uniform within each aligned k-block).
__global__ void k_localsort() {
    __shared__ unsigned long long s[2048];
    int b = blockIdx.y;
    int gbase = blockIdx.x * 2048;          // within-batch base
    int base  = b * NPAD + gbase;
    int tid = threadIdx.x;
    s[tid]        = g_sort[base + tid];
    s[tid + 1024] = g_sort[base + tid + 1024];
    for (int k = 2; k <= 2048; k <<= 1) {
        for (int j = k >> 1; j > 0; j >>= 1) {
            __syncthreads();
            int pos = 2 * tid - (tid & (j - 1));
            bool desc = (((gbase + pos) & k) == 0);
            unsigned long long a = s[pos], c = s[pos + j];
            if (desc ? (a < c) : (a > c)) { s[pos] = c; s[pos + j] = a; }
        }
    }
    __syncthreads();
    g_sort[base + tid]        = s[tid];
    g_sort[base + tid + 1024] = s[tid + 1024];
}

__global__ void k_gmerge(int k, int j) {
    int t = blockIdx.x * blockDim.x + threadIdx.x;  // 0..16383
    int b = blockIdx.y;
    int i = 2 * t - (t & (j - 1));
    bool desc = ((i & k) == 0);
    unsigned long long* p = g_sort + b * NPAD;
    unsigned long long a = p[i], c = p[i + j];
    if (desc ? (a < c) : (a > c)) { p[i] = c; p[i + j] = a; }
}

__global__ void k_lmerge(int k) {
    __shared__ unsigned long long s[2048];
    int b = blockIdx.y;
    int gbase = blockIdx.x * 2048;
    int base  = b * NPAD + gbase;
    int tid = threadIdx.x;
    s[tid]        = g_sort[base + tid];
    s[tid + 1024] = g_sort[base + tid + 1024];
    for (int j = 1024; j > 0; j >>= 1) {
        __syncthreads();
        int pos = 2 * tid - (tid & (j - 1));
        bool desc = (((gbase + pos) & k) == 0);
        unsigned long long a = s[pos], c = s[pos + j];
        if (desc ? (a < c) : (a > c)) { s[pos] = c; s[pos + j] = a; }
    }
    __syncthreads();
    g_sort[base + tid]        = s[tid];
    g_sort[base + tid + 1024] = s[tid + 1024];
}

// ---------------- 2) extract top-K, gather boxes, write keep ----------------
__global__ void k_extract(const float* __restrict__ box, float* __restrict__ out,
                          int write_keep) {
    int t = blockIdx.x * blockDim.x + threadIdx.x;
    if (t >= BATCH * KTOP) return;
    int b = t / KTOP;
    unsigned long long key = g_sort[b * NPAD + (t - b * KTOP)];
    int idx = (int)(0xFFFFFFFFu - (unsigned)(key & 0xFFFFFFFFull));
    float sc = __uint_as_float((unsigned)(key >> 32));
    g_topS[t] = sc;
    g_keep[t] = idx;
    g_flags[t] = 0u;
    const float* bb = box + b * 4 * NBOX;
    float x1 = bb[idx], y1 = bb[NBOX + idx], x2 = bb[2 * NBOX + idx], y2 = bb[3 * NBOX + idx];
    g_boxk[t] = make_float4(x1, y1, x2, y2);
    g_areak[t] = (x2 - x1) * (y2 - y1);
    if (write_keep) out[BATCH * KTOP + t] = (float)idx;   // keep as float
}

__global__ void k_gather(const float* __restrict__ feat) {
    int t = blockIdx.x * blockDim.x + threadIdx.x;
    if (t >= BATCH * CH * KP) return;
    int k = t % KP;
    int rem = t / KP;
    int c = rem % CH, b = rem / CH;
    float v = 0.f;
    if (k < KTOP) v = feat[(b * CH + c) * NBOX + g_keep[b * KTOP + k]];
    g_x0[t] = v;
}

// ---------------- 3) IoU local-max flags (division-free) ----------------
__global__ void k_iou() {
    int ti = blockIdx.x, tj = blockIdx.y, b = blockIdx.z;
    if (ti > tj) return;
    __shared__ float4 sbx[128];
    __shared__ float  sar[128];
    int tid = threadIdx.x;
    int gi0 = ti * 128;
    int gl = gi0 + tid;
    if (gl < KTOP) { sbx[tid] = g_boxk[b * KTOP + gl]; sar[tid] = g_areak[b * KTOP + gl]; }
    __syncthreads();
    int j = tj * 128 + tid;
    if (j >= KTOP) return;
    float4 bj = g_boxk[b * KTOP + j];
    float  aj = g_areak[b * KTOP + j];
    int imax = min(KTOP, min(j, gi0 + 128)) - gi0;   // valid i: gi<j, gi<KTOP
    unsigned int fl = 0u;
    for (int i = 0; i < imax; i++) {
        float4 bi = sbx[i];
        float w = fminf(bi.z, bj.z) - fmaxf(bi.x, bj.x);
        float h = fminf(bi.w, bj.w) - fmaxf(bi.y, bj.y);
        w = fmaxf(w, 0.f); h = fmaxf(h, 0.f);
        float inter = w * h;
        float uni = sar[i] + aj - inter;
        if (inter >= 0.4f * uni) fl |= 1u;
        if (inter >= 0.6f * uni) fl |= 2u;
        if (inter >= 0.8f * uni) fl |= 4u;
        if (fl == 7u) break;
    }
    if (fl) atomicOr(&g_flags[b * KTOP + j], fl);
}

// ---------------- 4) fp32 SGEMM layer: Y = LeakyReLU(W @ X + b) ----------------
// X,Y: [CH, KP] per batch row-major; W: [256,256] row-major (o,i); 128x128x16 tiles.
__global__ void __launch_bounds__(256, 2)
k_gemm(int phase, const float* __restrict__ Wl, const float* __restrict__ bl) {
    __shared__ float As[16][128];
    __shared__ float Bs[16][128];
    const float* X = phase ? g_x1 : g_x0;
    float*       Y = phase ? g_x0 : g_x1;
    int tid = threadIdx.x;
    int tx = tid & 15, ty = tid >> 4;
    int bx = blockIdx.x, by = blockIdx.y, bz = blockIdx.z;
    const float* A  = Wl + by * 128 * 256;
    const float* Bp = X + bz * CH * KP + bx * 128;
    float acc[8][8];
#pragma unroll
    for (int i = 0; i < 8; i++)
#pragma unroll
        for (int j = 0; j < 8; j++) acc[i][j] = 0.f;

    for (int kk = 0; kk < 256; kk += 16) {
#pragma unroll
        for (int r = 0; r < 2; r++) {
            int lin = tid + r * 256;
            int row = lin >> 2, kc = (lin & 3) * 4;
            float4 v = *(const float4*)(A + row * 256 + kk + kc);
            As[kc + 0][row] = v.x; As[kc + 1][row] = v.y;
            As[kc + 2][row] = v.z; As[kc + 3][row] = v.w;
        }
#pragma unroll
        for (int r = 0; r < 2; r++) {
            int lin = tid + r * 256;
            int row = lin >> 5, col = (lin & 31) * 4;
            *(float4*)(&Bs[row][col]) = *(const float4*)(Bp + (kk + row) * KP + col);
        }
        __syncthreads();
#pragma unroll
        for (int bk = 0; bk < 16; bk++) {
            float a[8], bv[8];
            *(float4*)(a)     = *(const float4*)(&As[bk][ty * 4]);
            *(float4*)(a + 4) = *(const float4*)(&As[bk][64 + ty * 4]);
            *(float4*)(bv)     = *(const float4*)(&Bs[bk][tx * 4]);
            *(float4*)(bv + 4) = *(const float4*)(&Bs[bk][64 + tx * 4]);
#pragma unroll
            for (int i = 0; i < 8; i++)
#pragma unroll
                for (int j = 0; j < 8; j++) acc[i][j] += a[i] * bv[j];
        }
        __syncthreads();
    }
    float* Yb = Y + bz * CH * KP;
#pragma unroll
    for (int i = 0; i < 8; i++) {
        int row = by * 128 + ((i < 4) ? (ty * 4 + i) : (64 + ty * 4 + i - 4));
        float bb = bl[row];
        float* yrow = Yb + row * KP + bx * 128;
#pragma unroll
        for (int half = 0; half < 2; half++) {
            int c0 = half ? (64 + tx * 4) : (tx * 4);
            float4 v;
            float t0 = acc[i][half * 4 + 0] + bb; v.x = t0 > 0.f ? t0 : 0.2f * t0;
            float t1 = acc[i][half * 4 + 1] + bb; v.y = t1 > 0.f ? t1 : 0.2f * t1;
            float t2 = acc[i][half * 4 + 2] + bb; v.z = t2 > 0.f ? t2 : 0.2f * t2;
            float t3 = acc[i][half * 4 + 3] + bb; v.w = t3 > 0.f ? t3 : 0.2f * t3;
            *(float4*)(yrow + c0) = v;
        }
    }
}

// ---------------- 5) final head: 3x256 proj + softmax + mask combine ----------------
__global__ void k_final(const float* __restrict__ Wf, const float* __restrict__ bf,
                        float* __restrict__ out) {
    int t = blockIdx.x * blockDim.x + threadIdx.x;
    int b = blockIdx.y;
    if (t >= KTOP) return;
    const float* X = g_x0 + b * CH * KP;   // after 6 layers result lives in g_x0
    float l0 = bf[0], l1 = bf[1], l2 = bf[2];
#pragma unroll 4
    for (int i = 0; i < CH; i++) {
        float xv = X[i * KP + t];
        l0 += Wf[i] * xv;
        l1 += Wf[256 + i] * xv;
        l2 += Wf[512 + i] * xv;
    }
    float m = fmaxf(l0, fmaxf(l1, l2));
    float e0 = expf(l0 - m), e1 = expf(l1 - m), e2 = expf(l2 - m);
    float inv = 1.f / (e0 + e1 + e2);
    unsigned int fl = g_flags[b * KTOP + t];
    float loc = 0.f;
    if (!(fl & 1u)) loc += e0 * inv;
    if (!(fl & 2u)) loc += e1 * inv;
    if (!(fl & 4u)) loc += e2 * inv;
    out[b * KTOP + t] = loc;
}

// ---------------- launch ----------------
extern "C" void kernel_launch(void* const* d_in, const int* in_sizes, int n_in,
                              void* d_out, int out_size) {
    const float* box   = (const float*)d_in[0];
    const float* score = (const float*)d_in[1];
    const float* feat  = (const float*)d_in[2];
    const float* W     = (const float*)d_in[3];
    const float* bvec  = (const float*)d_in[4];
    const float* Wf    = (const float*)d_in[5];
    const float* bf    = (const float*)d_in[6];
    float* out = (float*)d_out;
    int write_keep = (out_size >= 2 * BATCH * KTOP) ? 1 : 0;

    k_init<<<(BATCH * NPAD + 255) / 256, 256>>>(score);
    k_localsort<<<dim3(16, 2), 1024>>>();
    for (int k = 4096; k <= NPAD; k <<= 1) {
        for (int j = k >> 1; j >= 2048; j >>= 1)
            k_gmerge<<<dim3(64, 2), 256>>>(k, j);
        k_lmerge<<<dim3(16, 2), 1024>>>(k);
    }
    k_extract<<<(BATCH * KTOP + 255) / 256, 256>>>(box, out, write_keep);
    k_gather<<<(BATCH * CH * KP + 255) / 256, 256>>>(feat);
    k_iou<<<dim3(40, 40, BATCH), 128>>>();
    for (int l = 0; l < NLAYERS; l++)
        k_gemm<<<dim3(40, 2, BATCH), 256>>>(l & 1, W + l * 256 * 256, bvec + l * 256);
    k_final<<<dim3(40, BATCH), 128>>>(Wf, bf, out);
}

// round 4
// speedup vs baseline: 2.4921x; 2.4921x over previous
#include <cuda_runtime.h>
#include <cuda_bf16.h>
#include <cstdint>

#define BATCH 2
#define NBOX  20000
#define CH    256
#define KTOP  5000
#define NPAD  32768
#define KP    5120
#define NLAYERS 6

// ---------------- scratch (no allocations allowed) ----------------
__device__ unsigned long long g_sort[BATCH * NPAD];
__device__ int            g_keep[BATCH * KTOP];
__device__ float4         g_boxk[BATCH * KTOP];
__device__ float          g_areak[BATCH * KTOP];
__device__ unsigned int   g_flags[BATCH * KTOP];
__device__ __nv_bfloat16  g_xb0[BATCH * KP * CH];
__device__ __nv_bfloat16  g_xb1[BATCH * KP * CH];
__device__ __nv_bfloat16  g_Wbf[NLAYERS * CH * CH];

__device__ __forceinline__ uint32_t smem_u32(const void* p) {
    uint32_t a;
    asm("{ .reg .u64 t; cvta.to.shared.u64 t, %1; cvt.u32.u64 %0, t; }" : "=r"(a) : "l"(p));
    return a;
}

// ---------------- 0) convert W to bf16 ----------------
__global__ void k_prep(const float* __restrict__ W) {
    int i = blockIdx.x * blockDim.x + threadIdx.x;
    if (i < NLAYERS * CH * CH) g_Wbf[i] = __float2bfloat16_rn(W[i]);
}

// ---------------- 1) sort: key = score_bits<<32 | ~idx, descending bitonic ----------------
__global__ void k_init(const float* __restrict__ score) {
    int i = blockIdx.x * blockDim.x + threadIdx.x;
    if (i >= BATCH * NPAD) return;
    int b = i >> 15, n = i & (NPAD - 1);
    unsigned long long key = 0ull;
    if (n < NBOX) {
        unsigned int bits = __float_as_uint(score[b * NBOX + n]);
        key = ((unsigned long long)bits << 32) | (0xFFFFFFFFu - (unsigned)n);
    }
    g_sort[i] = key;
}

__global__ void k_localsort() {
    __shared__ unsigned long long s[2048];
    int b = blockIdx.y;
    int gbase = blockIdx.x * 2048;
    int base  = b * NPAD + gbase;
    int tid = threadIdx.x;
    s[tid]        = g_sort[base + tid];
    s[tid + 1024] = g_sort[base + tid + 1024];
    for (int k = 2; k <= 2048; k <<= 1) {
        for (int j = k >> 1; j > 0; j >>= 1) {
            __syncthreads();
            int pos = 2 * tid - (tid & (j - 1));
            bool desc = (((gbase + pos) & k) == 0);
            unsigned long long a = s[pos], c = s[pos + j];
            if (desc ? (a < c) : (a > c)) { s[pos] = c; s[pos + j] = a; }
        }
    }
    __syncthreads();
    g_sort[base + tid]        = s[tid];
    g_sort[base + tid + 1024] = s[tid + 1024];
}

__global__ void k_gmerge(int k, int j) {
    int t = blockIdx.x * blockDim.x + threadIdx.x;
    int b = blockIdx.y;
    int i = 2 * t - (t & (j - 1));
    bool desc = ((i & k) == 0);
    unsigned long long* p = g_sort + b * NPAD;
    unsigned long long a = p[i], c = p[i + j];
    if (desc ? (a < c) : (a > c)) { p[i] = c; p[i + j] = a; }
}

__global__ void k_lmerge(int k) {
    __shared__ unsigned long long s[2048];
    int b = blockIdx.y;
    int gbase = blockIdx.x * 2048;
    int base  = b * NPAD + gbase;
    int tid = threadIdx.x;
    s[tid]        = g_sort[base + tid];
    s[tid + 1024] = g_sort[base + tid + 1024];
    for (int j = 1024; j > 0; j >>= 1) {
        __syncthreads();
        int pos = 2 * tid - (tid & (j - 1));
        bool desc = (((gbase + pos) & k) == 0);
        unsigned long long a = s[pos], c = s[pos + j];
        if (desc ? (a < c) : (a > c)) { s[pos] = c; s[pos + j] = a; }
    }
    __syncthreads();
    g_sort[base + tid]        = s[tid];
    g_sort[base + tid + 1024] = s[tid + 1024];
}

// ---------------- 2) extract / gather ----------------
__global__ void k_extract(const float* __restrict__ box, float* __restrict__ out,
                          int write_keep) {
    int t = blockIdx.x * blockDim.x + threadIdx.x;
    if (t >= BATCH * KTOP) return;
    int b = t / KTOP;
    unsigned long long key = g_sort[b * NPAD + (t - b * KTOP)];
    int idx = (int)(0xFFFFFFFFu - (unsigned)(key & 0xFFFFFFFFull));
    g_keep[t] = idx;
    g_flags[t] = 0u;
    const float* bb = box + b * 4 * NBOX;
    float x1 = bb[idx], y1 = bb[NBOX + idx], x2 = bb[2 * NBOX + idx], y2 = bb[3 * NBOX + idx];
    g_boxk[t] = make_float4(x1, y1, x2, y2);
    g_areak[t] = (x2 - x1) * (y2 - y1);
    if (write_keep) out[BATCH * KTOP + t] = (float)idx;
}

// token-major bf16 gather: g_xb0[b][t][c], one warp per token; pad tokens zeroed
__global__ void k_gather(const float* __restrict__ feat) {
    int w = (blockIdx.x * blockDim.x + threadIdx.x) >> 5;
    int lane = threadIdx.x & 31;
    if (w >= BATCH * KP) return;
    int b = w / KP, t = w - b * KP;
    uint4* dst = (uint4*)(g_xb0 + (size_t)w * CH);
    if (t >= KTOP) { dst[lane] = make_uint4(0, 0, 0, 0); return; }
    int idx = g_keep[b * KTOP + t];
    const float* f = feat + (size_t)b * CH * NBOX + idx;
    __nv_bfloat16 h[8];
#pragma unroll
    for (int q = 0; q < 8; q++)
        h[q] = __float2bfloat16_rn(f[(size_t)(lane * 8 + q) * NBOX]);
    dst[lane] = *(uint4*)h;
}

// ---------------- 3) IoU local-max flags (division-free) ----------------
__global__ void k_iou() {
    int ti = blockIdx.x, tj = blockIdx.y, b = blockIdx.z;
    if (ti > tj) return;
    __shared__ float4 sbx[128];
    __shared__ float  sar[128];
    int tid = threadIdx.x;
    int gi0 = ti * 128;
    int gl = gi0 + tid;
    if (gl < KTOP) { sbx[tid] = g_boxk[b * KTOP + gl]; sar[tid] = g_areak[b * KTOP + gl]; }
    __syncthreads();
    int j = tj * 128 + tid;
    if (j >= KTOP) return;
    float4 bj = g_boxk[b * KTOP + j];
    float  aj = g_areak[b * KTOP + j];
    int imax = min(KTOP, min(j, gi0 + 128)) - gi0;
    unsigned int fl = 0u;
    for (int i = 0; i < imax; i++) {
        float4 bi = sbx[i];
        float w = fminf(bi.z, bj.z) - fmaxf(bi.x, bj.x);
        float h = fminf(bi.w, bj.w) - fmaxf(bi.y, bj.y);
        w = fmaxf(w, 0.f); h = fmaxf(h, 0.f);
        float inter = w * h;
        float uni = sar[i] + aj - inter;
        if (inter >= 0.4f * uni) fl |= 1u;
        if (inter >= 0.6f * uni) fl |= 2u;
        if (inter >= 0.8f * uni) fl |= 4u;
        if (fl == 7u) break;
    }
    if (fl) atomicOr(&g_flags[b * KTOP + j], fl);
}

// ---------------- 4) bf16 mma.sync layer ----------------
// Y[t][o] = LeakyReLU(sum_k W[o][k] * X[t][k] + b[o])
// CTA tile: 128 tokens (M) x 128 out-ch (N) x K=256, smem-resident.
// smem rows padded to 528B (odd*16B) -> conflict-free ldmatrix.
#define ROWB   528
#define TILEB  (128 * ROWB)            // 67584
#define SMEM_GEMM (2 * TILEB + 512)    // X tile, W tile, bias

__device__ __forceinline__ void ldm4(uint32_t* r, uint32_t addr) {
    asm volatile("ldmatrix.sync.aligned.m8n8.x4.shared.b16 {%0,%1,%2,%3}, [%4];"
                 : "=r"(r[0]), "=r"(r[1]), "=r"(r[2]), "=r"(r[3]) : "r"(addr));
}
__device__ __forceinline__ void mma16816(float* c, const uint32_t* a,
                                         uint32_t b0, uint32_t b1) {
    asm volatile(
        "mma.sync.aligned.m16n8k16.row.col.f32.bf16.bf16.f32 "
        "{%0,%1,%2,%3}, {%4,%5,%6,%7}, {%8,%9}, {%0,%1,%2,%3};"
        : "+f"(c[0]), "+f"(c[1]), "+f"(c[2]), "+f"(c[3])
        : "r"(a[0]), "r"(a[1]), "r"(a[2]), "r"(a[3]), "r"(b0), "r"(b1));
}

__global__ void __launch_bounds__(256, 1)
k_mma(const __nv_bfloat16* __restrict__ Xin, __nv_bfloat16* __restrict__ Yout,
      int layer, const float* __restrict__ bvec) {
    extern __shared__ char smem[];
    float* sbias = (float*)(smem + 2 * TILEB);
    uint32_t sx = smem_u32(smem);
    uint32_t sw = sx + TILEB;
    int tid = threadIdx.x, wid = tid >> 5, lane = tid & 31;
    int bx = blockIdx.x, by = blockIdx.y, bz = blockIdx.z;

    const uint4* gX = (const uint4*)(Xin + ((size_t)bz * KP + (size_t)bx * 128) * CH);
    const uint4* gW = (const uint4*)(g_Wbf + (size_t)layer * CH * CH + (size_t)by * 128 * CH);
#pragma unroll
    for (int it = 0; it < 16; it++) {
        int c = tid + it * 256;            // 4096 chunks of 8 bf16 per tile
        int row = c >> 5, ch = (c & 31) * 8;
        *(uint4*)(smem + row * ROWB + ch * 2)         = gX[c];
        *(uint4*)(smem + TILEB + row * ROWB + ch * 2) = gW[c];
    }
    if (tid < 128) sbias[tid] = bvec[layer * CH + by * 128 + tid];
    __syncthreads();

    int wm = wid & 3, wn = wid >> 2;       // 4 x 2 warp grid; warp tile 32(M) x 64(N)
    float acc[2][8][4];
#pragma unroll
    for (int i = 0; i < 2; i++)
#pragma unroll
        for (int j = 0; j < 8; j++)
#pragma unroll
            for (int q = 0; q < 4; q++) acc[i][j][q] = 0.f;

    // per-lane ldmatrix patterns
    int a_row  = lane & 15;                 // lanes 0-15 rows 0-15 (k lo), 16-31 same rows (k hi)
    int a_koff = (lane >> 4) * 8;
    int b_row  = (lane & 7) + ((lane >> 4) << 3);   // n-octet select on bit4
    int b_koff = ((lane >> 3) & 1) * 8;             // k-octet select on bit3
    uint32_t xbase = sx + (uint32_t)(wm * 32) * ROWB;
    uint32_t wbase = sw + (uint32_t)(wn * 64) * ROWB;

#pragma unroll 4
    for (int kk = 0; kk < 256; kk += 16) {
        uint32_t a[2][4];
#pragma unroll
        for (int mi = 0; mi < 2; mi++)
            ldm4(a[mi], xbase + (uint32_t)(mi * 16 + a_row) * ROWB + (kk + a_koff) * 2);
        uint32_t bfr[4][4];
#pragma unroll
        for (int ni = 0; ni < 4; ni++)
            ldm4(bfr[ni], wbase + (uint32_t)(ni * 16 + b_row) * ROWB + (kk + b_koff) * 2);
#pragma unroll
        for (int mi = 0; mi < 2; mi++)
#pragma unroll
            for (int nj = 0; nj < 8; nj++)
                mma16816(acc[mi][nj], a[mi], bfr[nj >> 1][(nj & 1) * 2],
                         bfr[nj >> 1][(nj & 1) * 2 + 1]);
    }

    // epilogue: bias + LeakyReLU, packed bf16x2 stores, token-major out
    int tq = lane >> 2, tr = lane & 3;
    __nv_bfloat16* Yb = Yout + ((size_t)bz * KP + (size_t)bx * 128) * CH + (size_t)by * 128;
#pragma unroll
    for (int mi = 0; mi < 2; mi++) {
#pragma unroll
        for (int nj = 0; nj < 8; nj++) {
            int n = wn * 64 + nj * 8 + tr * 2;
            float b0v = sbias[n], b1v = sbias[n + 1];
            int m0 = wm * 32 + mi * 16 + tq;
#pragma unroll
            for (int h = 0; h < 2; h++) {        // rows m0 and m0+8
                float v0 = acc[mi][nj][h * 2 + 0] + b0v;
                float v1 = acc[mi][nj][h * 2 + 1] + b1v;
                v0 = v0 > 0.f ? v0 : 0.2f * v0;
                v1 = v1 > 0.f ? v1 : 0.2f * v1;
                __nv_bfloat162 pk;
                pk.x = __float2bfloat16_rn(v0);
                pk.y = __float2bfloat16_rn(v1);
                *(__nv_bfloat162*)(Yb + (size_t)(m0 + h * 8) * CH + n) = pk;
            }
        }
    }
}

// ---------------- 5) final head: warp per token ----------------
__global__ void k_final(const float* __restrict__ Wf, const float* __restrict__ bf,
                        float* __restrict__ out) {
    int w = (blockIdx.x * blockDim.x + threadIdx.x) >> 5;
    int lane = threadIdx.x & 31;
    if (w >= BATCH * KTOP) return;
    int b = w / KTOP, t = w - b * KTOP;
    const uint4* x = (const uint4*)(g_xb0 + ((size_t)b * KP + t) * CH);
    uint4 raw = x[lane];
    __nv_bfloat16 h[8];
    *(uint4*)h = raw;
    float l0 = 0.f, l1 = 0.f, l2 = 0.f;
    int c0 = lane * 8;
#pragma unroll
    for (int q = 0; q < 8; q++) {
        float xv = __bfloat162float(h[q]);
        l0 += Wf[c0 + q] * xv;
        l1 += Wf[CH + c0 + q] * xv;
        l2 += Wf[2 * CH + c0 + q] * xv;
    }
#pragma unroll
    for (int o = 16; o; o >>= 1) {
        l0 += __shfl_xor_sync(0xFFFFFFFFu, l0, o);
        l1 += __shfl_xor_sync(0xFFFFFFFFu, l1, o);
        l2 += __shfl_xor_sync(0xFFFFFFFFu, l2, o);
    }
    if (lane == 0) {
        l0 += bf[0]; l1 += bf[1]; l2 += bf[2];
        float m = fmaxf(l0, fmaxf(l1, l2));
        float e0 = expf(l0 - m), e1 = expf(l1 - m), e2 = expf(l2 - m);
        float inv = 1.f / (e0 + e1 + e2);
        unsigned int fl = g_flags[b * KTOP + t];
        float loc = 0.f;
        if (!(fl & 1u)) loc += e0 * inv;
        if (!(fl & 2u)) loc += e1 * inv;
        if (!(fl & 4u)) loc += e2 * inv;
        out[b * KTOP + t] = loc;
    }
}

// ---------------- launch ----------------
extern "C" void kernel_launch(void* const* d_in, const int* in_sizes, int n_in,
                              void* d_out, int out_size) {
    const float* box   = (const float*)d_in[0];
    const float* score = (const float*)d_in[1];
    const float* feat  = (const float*)d_in[2];
    const float* W     = (const float*)d_in[3];
    const float* bvec  = (const float*)d_in[4];
    const float* Wf    = (const float*)d_in[5];
    const float* bf    = (const float*)d_in[6];
    float* out = (float*)d_out;
    int write_keep = (out_size >= 2 * BATCH * KTOP) ? 1 : 0;

    static int init_done = 0;
    static __nv_bfloat16 *x0p = nullptr, *x1p = nullptr;
    if (!init_done) {
        cudaFuncSetAttribute(k_mma, cudaFuncAttributeMaxDynamicSharedMemorySize, SMEM_GEMM);
        cudaGetSymbolAddress((void**)&x0p, g_xb0);
        cudaGetSymbolAddress((void**)&x1p, g_xb1);
        init_done = 1;
    }

    k_prep<<<(NLAYERS * CH * CH + 255) / 256, 256>>>(W);
    k_init<<<(BATCH * NPAD + 255) / 256, 256>>>(score);
    k_localsort<<<dim3(16, 2), 1024>>>();
    for (int k = 4096; k <= NPAD; k <<= 1) {
        for (int j = k >> 1; j >= 2048; j >>= 1)
            k_gmerge<<<dim3(64, 2), 256>>>(k, j);
        k_lmerge<<<dim3(16, 2), 1024>>>(k);
    }
    k_extract<<<(BATCH * KTOP + 255) / 256, 256>>>(box, out, write_keep);
    k_gather<<<BATCH * KP / 8, 256>>>(feat);            // 8 warps/block
    k_iou<<<dim3(40, 40, BATCH), 128>>>();
    for (int l = 0; l < NLAYERS; l++) {
        const __nv_bfloat16* Xi = (l & 1) ? x1p : x0p;
        __nv_bfloat16*       Yo = (l & 1) ? x0p : x1p;
        k_mma<<<dim3(KP / 128, 2, BATCH), 256, SMEM_GEMM>>>(Xi, Yo, l, bvec);
    }
    k_final<<<(BATCH * KTOP + 7) / 8, 256>>>(Wf, bf, out);
}